// round 6
// baseline (speedup 1.0000x reference)
#include <cuda_runtime.h>
#include <cuda_bf16.h>
#include <cstdint>
#include <math.h>

// ============================================================================
// Problem constants
// ============================================================================
#define LEADS       12
#define BATCH       16384
#define TOTAL_ROWS  (BATCH * LEADS)          // 196608
#define BPC         10                       // batches per CTA
#define ROWS_CTA    (BPC * LEADS)            // 120 (MMA-padded to 128)
#define NCTAS       ((BATCH + BPC - 1) / BPC)
#define THREADS     512

// smem layout (bytes)
#define H_OFF       2048                     // H: 120 x 256 packed u32 (1024B/row)
#define A_OFF       (H_OFF + ROWS_CTA * 1024)       // 124928
#define ABUF        16384                    // 128 rows x 128B (32 packed k)
#define B_OFF       (A_OFF + 2 * ABUF)              // 157696
#define BBUF        32768                    // 256 rows x 128B
#define SMEM_TOTAL  (B_OFF + 2 * BBUF)              // 223232

// swizzled tile addressing: row*128B + 8B-granule xor
#define SWZ(row, kb) ((row) * 128 + ((kb) ^ (((row) & 7) << 3)))

// ============================================================================
// Device scratch: packed (hi | lo<<16) bf16 weights, transposed [n][k]
// ============================================================================
__device__ uint32_t g_W1p[256 * 512];
__device__ uint32_t g_W2p[256 * 256];
__device__ uint32_t g_W3p[128 * 256];

// ============================================================================
// Helpers
// ============================================================================
__device__ __forceinline__ uint32_t prmt(uint32_t a, uint32_t b, uint32_t s) {
    uint32_t d;
    asm("prmt.b32 %0, %1, %2, %3;" : "=r"(d) : "r"(a), "r"(b), "r"(s));
    return d;
}

// m16n8k16 row.col bf16 MMA, fp32 accumulate (baseline sm_80+ PTX — no 'a' gate)
__device__ __forceinline__ void mma_bf16(float* c, uint32_t a0, uint32_t a1,
                                         uint32_t a2, uint32_t a3,
                                         uint32_t b0, uint32_t b1) {
    asm volatile(
        "mma.sync.aligned.m16n8k16.row.col.f32.bf16.bf16.f32 "
        "{%0,%1,%2,%3}, {%4,%5,%6,%7}, {%8,%9}, {%0,%1,%2,%3};"
        : "+f"(c[0]), "+f"(c[1]), "+f"(c[2]), "+f"(c[3])
        : "r"(a0), "r"(a1), "r"(a2), "r"(a3), "r"(b0), "r"(b1));
}

__device__ __forceinline__ void cp_async8(uint32_t smem_dst, const void* gsrc) {
    asm volatile("cp.async.ca.shared.global [%0], [%1], 8;\n"
                 :: "r"(smem_dst), "l"(gsrc));
}
__device__ __forceinline__ uint32_t smem_u32(const void* p) {
    uint32_t a;
    asm("{ .reg .u64 t; cvta.to.shared.u64 t, %1; cvt.u32.u64 %0, t; }"
        : "=r"(a) : "l"(p));
    return a;
}

// fp32 -> packed (hi bf16 | lo bf16 << 16), lo = residual
__device__ __forceinline__ uint32_t f2pack(float v) {
    __nv_bfloat16 h = __float2bfloat16(v);
    float hf = __bfloat162float(h);
    __nv_bfloat16 l = __float2bfloat16(v - hf);
    unsigned short hu = *(unsigned short*)&h, lu = *(unsigned short*)&l;
    return (uint32_t)hu | ((uint32_t)lu << 16);
}

// ============================================================================
// Weight prep: W(K,N) fp32 -> packed hi/lo bf16, transposed [n][k]
// ============================================================================
__global__ void prep_weights(const float* __restrict__ W1,
                             const float* __restrict__ W2,
                             const float* __restrict__ W3) {
    int i = blockIdx.x * 256 + threadIdx.x;
    if (i < 512 * 256) {
        int k = i / 256, n = i % 256;
        g_W1p[n * 512 + k] = f2pack(W1[i]);
    } else if (i < 512 * 256 + 256 * 256) {
        int j = i - 512 * 256;
        int k = j / 256, n = j % 256;
        g_W2p[n * 256 + k] = f2pack(W2[j]);
    } else if (i < 512 * 256 + 256 * 256 + 256 * 128) {
        int j = i - 512 * 256 - 256 * 256;
        int k = j / 128, n = j % 128;
        g_W3p[n * 256 + k] = f2pack(W3[j]);
    }
}

// ============================================================================
// One GCN layer: S = Ain * W  (Ain = X for L1, relu(Amix*S_prev + b) for L2/3,
// mixing folded into A-tile staging). Raw S written packed to H (L1/L2) or
// fp32 to S3 staging (L3). 3-pass bf16 split: hh + hl + lh.
// ============================================================================
template<int LAYER>
__device__ __forceinline__ void run_layer(char* smem, uint32_t sb,
                                          const float* __restrict__ x,
                                          const float* __restrict__ bmix,
                                          long long row0)
{
    constexpr int KT   = (LAYER == 1) ? 512 : 256;
    constexpr int NOUT = (LAYER == 3) ? 128 : 256;
    constexpr int NT   = KT / 32;                 // k chunks of 32
    constexpr int NTPJ = (LAYER == 3) ? 4 : 8;    // n-tiles per warp job

    const int tid  = threadIdx.x;
    const int wid  = tid >> 5;
    const int lane = tid & 31;
    const int gq   = lane >> 2;        // fragment group row
    const int qt   = lane & 3;         // fragment group col
    const int mtA  = (wid >> 2) * 16;  // m-tile pair row bases
    const int mtB  = mtA + 64;
    const int ng   = wid & 3;

    const uint32_t* Wp = (LAYER == 1) ? g_W1p : (LAYER == 2) ? g_W2p : g_W3p;
    const float* As = (const float*)smem;

    float acc[2][NTPJ][4];
    #pragma unroll
    for (int j = 0; j < 2; j++)
        #pragma unroll
        for (int j2 = 0; j2 < NTPJ; j2++)
            #pragma unroll
            for (int e = 0; e < 4; e++) acc[j][j2][e] = 0.f;

    float2 av[4];   // layer-1 X prefetch registers

    // -- staging helpers ----------------------------------------------------
    auto stage_b = [&](int t, int bufi) {
        const uint32_t bbase = sb + B_OFF + bufi * BBUF;
        #pragma unroll
        for (int i = 0; i < (NOUT * 16) / THREADS; i++) {
            int gI = tid + i * THREADS;
            int n = gI >> 4, kq = gI & 15;
            cp_async8(bbase + SWZ(n, kq * 8),
                      Wp + (size_t)n * KT + t * 32 + kq * 2);
        }
        asm volatile("cp.async.commit_group;\n");
    };
    auto a1_issue = [&](int t) {
        #pragma unroll
        for (int i = 0; i < 4; i++) {
            int gI = tid + i * THREADS;
            int r = gI >> 4, kp = gI & 15;
            long long grow = row0 + r;
            av[i] = make_float2(0.f, 0.f);
            if (r < ROWS_CTA && grow < TOTAL_ROWS)
                av[i] = *(const float2*)(x + grow * 512 + t * 32 + 2 * kp);
        }
    };
    auto a1_store = [&](int bufi) {
        char* Abw = smem + A_OFF + bufi * ABUF;
        #pragma unroll
        for (int i = 0; i < 4; i++) {
            int gI = tid + i * THREADS;
            int r = gI >> 4, kp = gI & 15;
            *(uint2*)(Abw + SWZ(r, kp * 8)) =
                make_uint2(f2pack(av[i].x), f2pack(av[i].y));
        }
    };
    // L2/L3: stage A chunk from H with fused 12x12 mixing + bias + relu
    auto a23_stage = [&](int t, int bufi) {
        char* Abw = smem + A_OFF + bufi * ABUF;
        #pragma unroll
        for (int i = 0; i < 4; i++) {
            int gI = tid + i * THREADS;
            int r = gI >> 4, kp = gI & 15;
            uint2 o = make_uint2(0u, 0u);
            if (r < ROWS_CTA) {
                int nlead = r - (r / 12) * 12;
                int rb = r - nlead;
                int c0 = t * 32 + 2 * kp;
                float s0 = bmix[c0], s1 = bmix[c0 + 1];
                const char* Hp = smem + H_OFF + rb * 1024 + c0 * 4;
                #pragma unroll
                for (int m = 0; m < 12; m++) {
                    uint2 hp = *(const uint2*)(Hp + m * 1024);
                    float f0 = __uint_as_float(hp.x << 16)
                             + __uint_as_float(hp.x & 0xFFFF0000u);
                    float f1 = __uint_as_float(hp.y << 16)
                             + __uint_as_float(hp.y & 0xFFFF0000u);
                    float a = As[nlead * 12 + m];
                    s0 = fmaf(a, f0, s0);
                    s1 = fmaf(a, f1, s1);
                }
                s0 = fmaxf(s0, 0.f);
                s1 = fmaxf(s1, 0.f);
                o = make_uint2(f2pack(s0), f2pack(s1));
            }
            *(uint2*)(Abw + SWZ(r, kp * 8)) = o;
        }
    };
    // -- compute one 32-wide k chunk ----------------------------------------
    auto compute = [&](int bufi) {
        const char* Ab = smem + A_OFF + bufi * ABUF;
        const char* Bb = smem + B_OFF + bufi * BBUF;
        #pragma unroll
        for (int ks = 0; ks < 32; ks += 16) {
            const int kb0 = (ks + 2 * qt) * 4;
            uint32_t Ah[2][4], Al[2][4];
            #pragma unroll
            for (int j = 0; j < 2; j++) {
                const int rb = j ? mtB : mtA;
                const int r1 = rb + gq, r2 = r1 + 8;
                uint2 p;
                p = *(const uint2*)(Ab + SWZ(r1, kb0));
                Ah[j][0] = prmt(p.x, p.y, 0x5410); Al[j][0] = prmt(p.x, p.y, 0x7632);
                p = *(const uint2*)(Ab + SWZ(r2, kb0));
                Ah[j][1] = prmt(p.x, p.y, 0x5410); Al[j][1] = prmt(p.x, p.y, 0x7632);
                p = *(const uint2*)(Ab + SWZ(r1, kb0 + 32));
                Ah[j][2] = prmt(p.x, p.y, 0x5410); Al[j][2] = prmt(p.x, p.y, 0x7632);
                p = *(const uint2*)(Ab + SWZ(r2, kb0 + 32));
                Ah[j][3] = prmt(p.x, p.y, 0x5410); Al[j][3] = prmt(p.x, p.y, 0x7632);
            }
            #pragma unroll
            for (int j2 = 0; j2 < NTPJ; j2++) {
                const int n = (ng * NTPJ + j2) * 8 + gq;
                uint2 p0 = *(const uint2*)(Bb + SWZ(n, kb0));
                uint2 p1 = *(const uint2*)(Bb + SWZ(n, kb0 + 32));
                uint32_t bh0 = prmt(p0.x, p0.y, 0x5410);
                uint32_t bl0 = prmt(p0.x, p0.y, 0x7632);
                uint32_t bh1 = prmt(p1.x, p1.y, 0x5410);
                uint32_t bl1 = prmt(p1.x, p1.y, 0x7632);
                #pragma unroll
                for (int j = 0; j < 2; j++) {
                    mma_bf16(acc[j][j2], Ah[j][0], Ah[j][1], Ah[j][2], Ah[j][3], bh0, bh1);
                    mma_bf16(acc[j][j2], Ah[j][0], Ah[j][1], Ah[j][2], Ah[j][3], bl0, bl1);
                    mma_bf16(acc[j][j2], Al[j][0], Al[j][1], Al[j][2], Al[j][3], bh0, bh1);
                }
            }
        }
    };

    // -- prologue: chunk 0 --------------------------------------------------
    stage_b(0, 0);
    if (LAYER == 1) { a1_issue(0); a1_store(0); }
    else            { a23_stage(0, 0); }
    asm volatile("cp.async.wait_group 0;\n" ::: "memory");
    __syncthreads();

    // -- mainloop: overlap B cp.async + L1 X-LDG with MMA -------------------
    #pragma unroll 1
    for (int t = 0; t < NT; t++) {
        const int cur = t & 1, nxt = cur ^ 1;
        if (t + 1 < NT) {
            stage_b(t + 1, nxt);
            if (LAYER == 1) a1_issue(t + 1);
        }
        compute(cur);
        if (t + 1 < NT) {
            if (LAYER == 1) a1_store(nxt);
            else            a23_stage(t + 1, nxt);
        }
        asm volatile("cp.async.wait_group 0;\n" ::: "memory");
        __syncthreads();
    }

    // -- epilogue: register-local writeback (raw S, no mixing) --------------
    if (LAYER < 3) {
        #pragma unroll
        for (int j = 0; j < 2; j++) {
            const int rb = j ? mtB : mtA;
            const int r1 = rb + gq, r2 = r1 + 8;
            #pragma unroll
            for (int j2 = 0; j2 < NTPJ; j2++) {
                const int c = (ng * NTPJ + j2) * 8 + qt * 2;
                if (r1 < ROWS_CTA)
                    *(uint2*)(smem + H_OFF + r1 * 1024 + c * 4) =
                        make_uint2(f2pack(acc[j][j2][0]), f2pack(acc[j][j2][1]));
                if (r2 < ROWS_CTA)
                    *(uint2*)(smem + H_OFF + r2 * 1024 + c * 4) =
                        make_uint2(f2pack(acc[j][j2][2]), f2pack(acc[j][j2][3]));
            }
        }
    } else {
        float* S3 = (float*)(smem + A_OFF);     // reuse dead A/B bufs, stride 132
        #pragma unroll
        for (int j = 0; j < 2; j++) {
            const int rb = j ? mtB : mtA;
            const int r1 = rb + gq, r2 = r1 + 8;
            #pragma unroll
            for (int j2 = 0; j2 < NTPJ; j2++) {
                const int c = (ng * NTPJ + j2) * 8 + qt * 2;
                *(float2*)&S3[r1 * 132 + c] = make_float2(acc[j][j2][0], acc[j][j2][1]);
                *(float2*)&S3[r2 * 132 + c] = make_float2(acc[j][j2][2], acc[j][j2][3]);
            }
        }
    }
    __syncthreads();
}

// ============================================================================
// Fused kernel: all 3 layers + final mixing/pooling
// ============================================================================
__global__ void __launch_bounds__(THREADS, 1)
ecg_mma_kernel(const float* __restrict__ x,
               const float* __restrict__ b1, const float* __restrict__ b2,
               const float* __restrict__ b3, float* __restrict__ out)
{
    extern __shared__ char smem[];
    const uint32_t sb = smem_u32(smem);
    float* As = (float*)smem;
    const int tid = threadIdx.x;
    const long long row0 = (long long)blockIdx.x * ROWS_CTA;

    // A_norm = D^{-1/2} (adj + 2I) D^{-1/2}
    if (tid == 0) {
        const signed char ei[15] = {0,0,1,0,1,2,0,1,1,2,6,7,8,9,10};
        const signed char ej[15] = {1,2,2,3,3,3,4,4,5,5,7,8,9,10,11};
        for (int k = 0; k < 144; k++) As[k] = 0.f;
        for (int e = 0; e < 15; e++) {
            As[ei[e] * LEADS + ej[e]] = 1.f;
            As[ej[e] * LEADS + ei[e]] = 1.f;
        }
        for (int i = 0; i < LEADS; i++) As[i * LEADS + i] = 2.f;
        float dinv[LEADS];
        for (int i = 0; i < LEADS; i++) {
            float s = 0.f;
            for (int j = 0; j < LEADS; j++) s += As[i * LEADS + j];
            dinv[i] = 1.0f / sqrtf(s);
        }
        for (int i = 0; i < LEADS; i++)
            for (int j = 0; j < LEADS; j++)
                As[i * LEADS + j] *= dinv[i] * dinv[j];
    }
    __syncthreads();

    run_layer<1>(smem, sb, x, nullptr, row0);   // S1 -> H (raw)
    run_layer<2>(smem, sb, nullptr, b1, row0);  // mix+b1+relu in staging; S2 -> H
    run_layer<3>(smem, sb, nullptr, b2, row0);  // mix+b2+relu in staging; S3 -> smem

    // final: out = [mean_n, max_n] of (Amix * S3 + b3)
    const float* S3 = (const float*)(smem + A_OFF);
    const int colg = tid & 63, rg = tid >> 6;
    const int c0 = 2 * colg;
    const float bva = b3[c0], bvb = b3[c0 + 1];

    for (int bb = rg; bb < BPC; bb += 8) {
        long long b = (long long)blockIdx.x * BPC + bb;
        if (b >= BATCH) break;
        float sm[LEADS][2];
        #pragma unroll
        for (int m = 0; m < LEADS; m++) {
            float2 v = *(const float2*)&S3[(bb * LEADS + m) * 132 + c0];
            sm[m][0] = v.x; sm[m][1] = v.y;
        }
        float mean0 = 0.f, mean1 = 0.f;
        float max0 = -INFINITY, max1 = -INFINITY;
        #pragma unroll
        for (int n = 0; n < LEADS; n++) {
            float h0 = bva, h1 = bvb;
            #pragma unroll
            for (int m = 0; m < LEADS; m++) {
                float a = As[n * LEADS + m];
                h0 = fmaf(a, sm[m][0], h0);
                h1 = fmaf(a, sm[m][1], h1);
            }
            mean0 += h0; mean1 += h1;
            max0 = fmaxf(max0, h0); max1 = fmaxf(max1, h1);
        }
        mean0 *= (1.f / 12.f);
        mean1 *= (1.f / 12.f);
        float* ob = out + b * 256;
        *(float2*)(ob + c0)       = make_float2(mean0, mean1);
        *(float2*)(ob + 128 + c0) = make_float2(max0, max1);
    }
}

// ============================================================================
// Launch
// ============================================================================
extern "C" void kernel_launch(void* const* d_in, const int* in_sizes, int n_in,
                              void* d_out, int out_size)
{
    const float* x  = (const float*)d_in[0];
    const float* W1 = (const float*)d_in[1];
    const float* b1 = (const float*)d_in[2];
    const float* W2 = (const float*)d_in[3];
    const float* b2 = (const float*)d_in[4];
    const float* W3 = (const float*)d_in[5];
    const float* b3 = (const float*)d_in[6];
    float* out = (float*)d_out;

    cudaFuncSetAttribute(ecg_mma_kernel,
                         cudaFuncAttributeMaxDynamicSharedMemorySize, SMEM_TOTAL);

    const int prep_elems = 512 * 256 + 256 * 256 + 256 * 128;
    prep_weights<<<(prep_elems + 255) / 256, 256>>>(W1, W2, W3);
    ecg_mma_kernel<<<NCTAS, THREADS, SMEM_TOTAL>>>(x, b1, b2, b3, out);
}